// round 14
// baseline (speedup 1.0000x reference)
#include <cuda_runtime.h>
#include <cuda_fp16.h>
#include <cstdint>
#include <cstring>

// NT-Xent contrastive loss, sm_103 baseline ISA. fp16 HMMA (f16 acc).
// Persistent fused kernel (148 CTAs): prep -> barrier -> symmetric-tile GEMM
// with EPILOGUE PIPELINED ONE TILE BEHIND THE MMA (tensor pipe stays fed while
// exp/rowsum of the previous tile issues) -> barrier -> distributed finish.

#define N2    8192
#define DD    128
#define NHALF 4096
#define RSTRIDE 272
#define TILE_SM (128 * RSTRIDE)          // 34816
#define SM_COLRED (4 * TILE_SM)          // A + 3 B stages before colred
#define SMEM_TOTAL (4 * TILE_SM + 1024)  // 140288
#define FXS  68719476736.0f              // 2^36
#define FXL  1099511627776.0f            // 2^40
#define NCTA 148

__device__ __align__(16) __half g_znA[(size_t)N2 * DD];  // * 2*log2(e)
__device__ __align__(16) __half g_znB[(size_t)N2 * DD];
__device__ unsigned long long g_S[N2];
__device__ unsigned long long g_acc;
__device__ unsigned int g_bar1, g_bar2, g_tick;
__device__ float g_pos[N2];
__device__ float g_diag[N2];

// ---------------- PTX helpers ----------------
__device__ __forceinline__ uint32_t smem_u32(const void* p) {
    uint32_t a;
    asm("{ .reg .u64 t; cvta.to.shared.u64 t, %1; cvt.u32.u64 %0, t; }" : "=r"(a) : "l"(p));
    return a;
}
__device__ __forceinline__ void cp16(uint32_t dst, const void* src) {
    asm volatile("cp.async.cg.shared.global [%0], [%1], 16;" :: "r"(dst), "l"(src));
}
#define CP_COMMIT() asm volatile("cp.async.commit_group;" ::: "memory")
#define CP_WAIT2()  asm volatile("cp.async.wait_group 2;" ::: "memory")
#define CP_WAIT1()  asm volatile("cp.async.wait_group 1;" ::: "memory")
#define CP_WAIT0()  asm volatile("cp.async.wait_group 0;" ::: "memory")

#define LDSM4(r0, r1, r2, r3, addr)                                              \
    asm volatile("ldmatrix.sync.aligned.m8n8.x4.shared.b16 {%0,%1,%2,%3}, [%4];" \
                 : "=r"(r0), "=r"(r1), "=r"(r2), "=r"(r3) : "r"(addr))

#define MMA16816H(c, a, b0, b1)                                                \
    asm volatile("mma.sync.aligned.m16n8k16.row.col.f16.f16.f16.f16 "          \
                 "{%0,%1}, {%2,%3,%4,%5}, {%6,%7}, {%0,%1};"                   \
                 : "+r"((c)[0]), "+r"((c)[1])                                  \
                 : "r"((a)[0]), "r"((a)[1]), "r"((a)[2]), "r"((a)[3]),         \
                   "r"(b0), "r"(b1))

__device__ __forceinline__ float fast_lg2(float x) {
    float y; asm("lg2.approx.f32 %0, %1;" : "=f"(y) : "f"(x)); return y;
}
__device__ __forceinline__ __half2 u2h2(uint32_t u) {
    __half2 h; memcpy(&h, &u, 4); return h;
}
__device__ __forceinline__ void global_barrier(unsigned int* ctr, int tid) {
    __threadfence();
    __syncthreads();
    if (tid == 0) {
        atomicAdd(ctr, 1u);
        while (atomicAdd(ctr, 0u) < NCTA) __nanosleep(64);
    }
    __syncthreads();
}

// ---------------- prep (one warp per pair) ----------------
__device__ __forceinline__ void prep_pair(const float* __restrict__ zi,
                                          const float* __restrict__ zj,
                                          int w, int lane) {
    float4 a = reinterpret_cast<const float4*>(zi + (size_t)w * DD)[lane];
    float4 b = reinterpret_cast<const float4*>(zj + (size_t)w * DD)[lane];
    float sa = a.x * a.x + a.y * a.y + a.z * a.z + a.w * a.w;
    float sb = b.x * b.x + b.y * b.y + b.z * b.z + b.w * b.w;
    float dp = a.x * b.x + a.y * b.y + a.z * b.z + a.w * b.w;
#pragma unroll
    for (int o = 16; o > 0; o >>= 1) {
        sa += __shfl_xor_sync(0xffffffffu, sa, o);
        sb += __shfl_xor_sync(0xffffffffu, sb, o);
        dp += __shfl_xor_sync(0xffffffffu, dp, o);
    }
    float ia = rsqrtf(sa), ib = rsqrtf(sb);
    const float CA = 2.8853900817779268f;   // 2*log2(e)
    float iaC = ia * CA, ibC = ib * CA;

    __half sA[4], pA[4], sB[4], pB[4];
    sA[0]=__float2half_rn(a.x*iaC); sA[1]=__float2half_rn(a.y*iaC);
    sA[2]=__float2half_rn(a.z*iaC); sA[3]=__float2half_rn(a.w*iaC);
    pA[0]=__float2half_rn(a.x*ia);  pA[1]=__float2half_rn(a.y*ia);
    pA[2]=__float2half_rn(a.z*ia);  pA[3]=__float2half_rn(a.w*ia);
    sB[0]=__float2half_rn(b.x*ibC); sB[1]=__float2half_rn(b.y*ibC);
    sB[2]=__float2half_rn(b.z*ibC); sB[3]=__float2half_rn(b.w*ibC);
    pB[0]=__float2half_rn(b.x*ib);  pB[1]=__float2half_rn(b.y*ib);
    pB[2]=__float2half_rn(b.z*ib);  pB[3]=__float2half_rn(b.w*ib);

    float da = 0.f, db = 0.f;
#pragma unroll
    for (int k = 0; k < 4; ++k) {
        da += __half2float(sA[k]) * __half2float(pA[k]);
        db += __half2float(sB[k]) * __half2float(pB[k]);
    }
#pragma unroll
    for (int o = 16; o > 0; o >>= 1) {
        da += __shfl_xor_sync(0xffffffffu, da, o);
        db += __shfl_xor_sync(0xffffffffu, db, o);
    }
    if (lane == 0) {
        float p = 2.0f * dp * ia * ib;
        g_pos[w] = p; g_pos[w + NHALF] = p;
        g_diag[w]         = exp2f(da);
        g_diag[w + NHALF] = exp2f(db);
    }
    uint2 u;
    memcpy(&u, sA, 8); reinterpret_cast<uint2*>(g_znA + (size_t)w * DD)[lane] = u;
    memcpy(&u, pA, 8); reinterpret_cast<uint2*>(g_znB + (size_t)w * DD)[lane] = u;
    memcpy(&u, sB, 8); reinterpret_cast<uint2*>(g_znA + (size_t)(w + NHALF) * DD)[lane] = u;
    memcpy(&u, pB, 8); reinterpret_cast<uint2*>(g_znB + (size_t)(w + NHALF) * DD)[lane] = u;
}

__device__ __forceinline__ void load_tile(uint32_t dstBase, const __half* src, int tid) {
#pragma unroll
    for (int p = 0; p < 8; ++p) {
        int id = p * 256 + tid;
        int row = id >> 4, ch = id & 15;
        cp16(dstBase + row * RSTRIDE + ch * 16,
             reinterpret_cast<const char*>(src) + row * 256 + ch * 16);
    }
}

// ---- MMA phase: all 128 HMMA of one tile into acc[np][mb][nb][2] (32 regs) ----
__device__ __forceinline__ void mma_tile(uint32_t bBase0,
                                         const uint32_t afr[4][8][4],
                                         uint32_t acc[2][4][2][2]) {
#pragma unroll
    for (int np = 0; np < 2; ++np) {
        const uint32_t bBase = bBase0 + (uint32_t)(np * 16) * RSTRIDE;
        uint32_t bfr[8][4];
        // ks-pipelined B loads (2 ahead) interleaved with MMAs: live ~3 buffers
        LDSM4(bfr[0][0], bfr[0][1], bfr[0][2], bfr[0][3], bBase);
        LDSM4(bfr[1][0], bfr[1][1], bfr[1][2], bfr[1][3], bBase + 32u);
#pragma unroll
        for (int ks = 0; ks < 8; ++ks) {
            if (ks + 2 < 8)
                LDSM4(bfr[ks + 2][0], bfr[ks + 2][1], bfr[ks + 2][2], bfr[ks + 2][3],
                      bBase + (uint32_t)((ks + 2) * 32));
#pragma unroll
            for (int mb = 0; mb < 4; ++mb) {
                MMA16816H(acc[np][mb][0], afr[mb][ks], bfr[ks][0], bfr[ks][1]);
                MMA16816H(acc[np][mb][1], afr[mb][ks], bfr[ks][2], bfr[ks][3]);
            }
        }
    }
}

// ---- Epilogue phase for a PREVIOUS tile's acc (no dependency on in-flight MMAs) ----
__device__ __forceinline__ void epi_tile(const uint32_t acc[2][4][2][2],
                                         int J, int I, float frow[4][2],
                                         float* colred, int tid, int lane,
                                         int wn, int wm) {
    const __half2 zero2 = __float2half2_rn(0.f);
    __half2 cs[2][2] = {{zero2, zero2}, {zero2, zero2}};
    __half2 sumr0[4] = {zero2, zero2, zero2, zero2};
    __half2 sumr8[4] = {zero2, zero2, zero2, zero2};
#pragma unroll
    for (int np = 0; np < 2; ++np)
#pragma unroll
        for (int mb = 0; mb < 4; ++mb)
#pragma unroll
            for (int nb = 0; nb < 2; ++nb) {
                __half2 e0 = h2exp2(u2h2(acc[np][mb][nb][0]));
                __half2 e1 = h2exp2(u2h2(acc[np][mb][nb][1]));
                sumr0[mb] = __hadd2(sumr0[mb], e0);
                sumr8[mb] = __hadd2(sumr8[mb], e1);
                cs[np][nb] = __hadd2(cs[np][nb], __hadd2(e0, e1));
            }
#pragma unroll
    for (int mb = 0; mb < 4; ++mb) {
        float2 f0 = __half22float2(sumr0[mb]);
        float2 f1 = __half22float2(sumr8[mb]);
        frow[mb][0] += f0.x + f0.y;
        frow[mb][1] += f1.x + f1.y;
    }
#pragma unroll
    for (int np = 0; np < 2; ++np)
#pragma unroll
        for (int nb = 0; nb < 2; ++nb) {
            __half2 v = cs[np][nb];
            v = __hadd2(v, __shfl_xor_sync(0xffffffffu, v, 4));
            v = __hadd2(v, __shfl_xor_sync(0xffffffffu, v, 8));
            v = __hadd2(v, __shfl_xor_sync(0xffffffffu, v, 16));
            if (lane < 4) {
                float2 f = __half22float2(v);
                int c = wn * 32 + np * 16 + nb * 8 + lane * 2;
                colred[wm * 128 + c + 0] = f.x;
                colred[wm * 128 + c + 1] = f.y;
            }
        }
    __syncthreads();   // colred ready
    if (J != I && tid < 128) {
        float v = colred[tid] + colred[128 + tid];
        atomicAdd(&g_S[J * 128 + tid], __float2ull_rn(v * FXS));
    }
}

// ---------------- fused persistent kernel ----------------
__global__ __launch_bounds__(256, 1) void fused_kernel(
    const float* __restrict__ zi, const float* __restrict__ zj,
    float* __restrict__ out) {
    extern __shared__ unsigned char smem[];
    const uint32_t sb   = smem_u32(smem);
    const uint32_t smA  = sb;
    const uint32_t smB0 = sb + TILE_SM;                          // 3 stages
    float* colred = reinterpret_cast<float*>(smem + SM_COLRED);  // [2 wm][128]

    const int tid = threadIdx.x, wid = tid >> 5, lane = tid & 31;
    const int wn = wid & 3, wm = wid >> 2;
    const int bx = blockIdx.x;

    // ======== phase 0: init + prep ========
    {
        int z = bx * 256 + tid;
        if (z < N2) g_S[z] = 0ull;
        if (z == 0) g_acc = 0ull;
        int gw = bx * 8 + wid;
#pragma unroll 1
        for (int w = gw; w < NHALF; w += NCTA * 8)
            prep_pair(zi, zj, w, lane);
    }
    global_barrier(&g_bar1, tid);

    // ======== phase 1: symmetric-tile GEMM, epilogue lagged one tile ========
    int t    = bx * 14 + (bx < 8 ? bx : 8);
    int tEnd = t + 14 + (bx < 8 ? 1 : 0);

    const uint32_t aOff = (uint32_t)(lane & 15) * RSTRIDE + (uint32_t)((lane >> 4) << 4);
    const uint32_t bOff = (uint32_t)((lane & 7) + ((lane & 16) ? 8 : 0)) * RSTRIDE +
                          (uint32_t)((lane & 8) ? 16 : 0);

#pragma unroll 1
    while (t < tEnd) {
        int q = t / 65, r = t - q * 65;
        int len1 = 64 - q;
        int I, J0, navail;
        if (r < len1) { I = q;      J0 = q + r;  navail = len1 - r; }
        else          { int r2 = r - len1;
                        I = 63 - q; J0 = I + r2; navail = (q + 1) - r2; }
        const int n = (tEnd - t < navail) ? (tEnd - t) : navail;
        t += n;

        __syncthreads();   // previous-run reads complete
        load_tile(smA, g_znA + (size_t)I * 128 * DD, tid);
        CP_COMMIT();
        load_tile(smB0, g_znB + (size_t)J0 * 128 * DD, tid);
        CP_COMMIT();
        if (n > 1)
            load_tile(smB0 + TILE_SM, g_znB + (size_t)(J0 + 1) * 128 * DD, tid);
        CP_COMMIT();
        CP_WAIT2();
        __syncthreads();

        uint32_t afr[4][8][4];
        {
            const uint32_t aBase = smA + (uint32_t)(wm * 64) * RSTRIDE + aOff;
#pragma unroll
            for (int mb = 0; mb < 4; ++mb)
#pragma unroll
                for (int ks = 0; ks < 8; ++ks)
                    LDSM4(afr[mb][ks][0], afr[mb][ks][1], afr[mb][ks][2], afr[mb][ks][3],
                          aBase + (uint32_t)(mb * 16) * RSTRIDE + (uint32_t)(ks * 32));
        }

        float frow[4][2] = {{0.f,0.f},{0.f,0.f},{0.f,0.f},{0.f,0.f}};
        uint32_t accA[2][4][2][2], accB[2][4][2][2];
        int Jpend = -1;

#pragma unroll 1
        for (int tt = 0; tt < n; ++tt) {
            const int J = J0 + tt;
            const int s = tt % 3;
            CP_WAIT1();
            __syncthreads();
            if (tt + 2 < n)
                load_tile(smB0 + (uint32_t)((tt + 2) % 3) * TILE_SM,
                          g_znB + (size_t)(J + 2) * 128 * DD, tid);
            CP_COMMIT();

            const uint32_t bBase0 = smB0 + (uint32_t)s * TILE_SM +
                                    (uint32_t)(wn * 32) * RSTRIDE + bOff;
            if ((tt & 1) == 0) {
#pragma unroll
                for (int np = 0; np < 2; ++np)
#pragma unroll
                    for (int mb = 0; mb < 4; ++mb)
#pragma unroll
                        for (int nb = 0; nb < 2; ++nb)
                            { accA[np][mb][nb][0] = 0u; accA[np][mb][nb][1] = 0u; }
                mma_tile(bBase0, afr, accA);                    // fills tensor pipe
                if (Jpend >= 0)
                    epi_tile(accB, Jpend, I, frow, colred, tid, lane, wn, wm);
            } else {
#pragma unroll
                for (int np = 0; np < 2; ++np)
#pragma unroll
                    for (int mb = 0; mb < 4; ++mb)
#pragma unroll
                        for (int nb = 0; nb < 2; ++nb)
                            { accB[np][mb][nb][0] = 0u; accB[np][mb][nb][1] = 0u; }
                mma_tile(bBase0, afr, accB);
                if (Jpend >= 0)
                    epi_tile(accA, Jpend, I, frow, colred, tid, lane, wn, wm);
            }
            Jpend = J;
        }
        // drain: epilogue for the final tile of the run
        if (((n - 1) & 1) == 0)
            epi_tile(accA, Jpend, I, frow, colred, tid, lane, wn, wm);
        else
            epi_tile(accB, Jpend, I, frow, colred, tid, lane, wn, wm);

        // row flush for band I (per run)
#pragma unroll
        for (int mb = 0; mb < 4; ++mb)
#pragma unroll
            for (int h = 0; h < 2; ++h) {
                frow[mb][h] += __shfl_xor_sync(0xffffffffu, frow[mb][h], 1);
                frow[mb][h] += __shfl_xor_sync(0xffffffffu, frow[mb][h], 2);
            }
        if ((lane & 3) == 0) {
            int qd = lane >> 2;
            int rbase = I * 128 + wm * 64 + qd;
#pragma unroll
            for (int mb = 0; mb < 4; ++mb) {
                atomicAdd(&g_S[rbase + mb * 16 + 0], __float2ull_rn(frow[mb][0] * FXS));
                atomicAdd(&g_S[rbase + mb * 16 + 8], __float2ull_rn(frow[mb][1] * FXS));
            }
        }
    }
    CP_WAIT0();
    global_barrier(&g_bar2, tid);

    // ======== phase 2: distributed finish ========
    {
        const float LN2 = 0.6931471805599453f;
        int i = bx * 256 + tid;
        unsigned long long fx = 0ull;
        if (i < N2) {
            float S = __ull2float_rn(__ldcg(&g_S[i])) * (1.0f / FXS);
            float term = fast_lg2(S - __ldcg(&g_diag[i])) * LN2 - __ldcg(&g_pos[i]);
            fx = __float2ull_rn(term * FXL);
        }
#pragma unroll
        for (int o = 16; o > 0; o >>= 1)
            fx += __shfl_xor_sync(0xffffffffu, fx, o);
        if (lane == 0 && fx != 0ull) atomicAdd(&g_acc, fx);
        __threadfence();
        __syncthreads();
        if (tid == 0) {
            unsigned int tk = atomicAdd(&g_tick, 1u);
            if (tk == NCTA - 1) {
                __threadfence();
                unsigned long long total = atomicAdd(&g_acc, 0ull);
                out[0] = (float)((double)total * (1.0 / 1099511627776.0) / (double)N2);
                g_bar1 = 0u; g_bar2 = 0u; g_tick = 0u;
            }
        }
    }
}

// ---------------- launch ----------------
extern "C" void kernel_launch(void* const* d_in, const int* in_sizes, int n_in,
                              void* d_out, int out_size) {
    const float* zi = (const float*)d_in[0];
    const float* zj = (const float*)d_in[1];
    cudaFuncSetAttribute(fused_kernel, cudaFuncAttributeMaxDynamicSharedMemorySize,
                         SMEM_TOTAL);
    fused_kernel<<<NCTA, 256, SMEM_TOTAL>>>(zi, zj, (float*)d_out);
}

// round 15
// speedup vs baseline: 1.0398x; 1.0398x over previous
#include <cuda_runtime.h>
#include <cuda_fp16.h>
#include <cstdint>
#include <cstring>

// NT-Xent contrastive loss, sm_103 baseline ISA. fp16 HMMA (f16 acc).
// Symmetric 128x128 tiles (I<=J), pair-major flattened schedule over 148 CTAs.
// Tile processed as 4 chunks of 16 cols with the exp2/rowsum epilogue of chunk
// c-1 issuing while chunk c's MMAs are in flight (register-lean: afr=64 regs,
// acc dbl-buffer=16 regs). Row sums -> band I, col sums -> band J, u64
// fixed-point atomics (deterministic). loss = mean( ln(S_i - diag_i) - pos_i ).

#define N2    8192
#define DD    128
#define NHALF 4096
#define RSTRIDE 272
#define TILE_SM (128 * RSTRIDE)          // 34816
#define SM_COLRED (4 * TILE_SM)          // A + 3 B stages before colred
#define SMEM_TOTAL (4 * TILE_SM + 2048)  // colred = 4*128 floats
#define FXS  68719476736.0f              // 2^36
#define FXL  1099511627776.0f            // 2^40
#define NCTA 148

__device__ __align__(16) __half g_znA[(size_t)N2 * DD];  // * 2*log2(e)
__device__ __align__(16) __half g_znB[(size_t)N2 * DD];
__device__ unsigned long long g_S[N2];
__device__ unsigned long long g_acc;
__device__ unsigned int g_tick;
__device__ float g_pos[N2];
__device__ float g_diag[N2];

// ---------------- PTX helpers ----------------
__device__ __forceinline__ uint32_t smem_u32(const void* p) {
    uint32_t a;
    asm("{ .reg .u64 t; cvta.to.shared.u64 t, %1; cvt.u32.u64 %0, t; }" : "=r"(a) : "l"(p));
    return a;
}
__device__ __forceinline__ void cp16(uint32_t dst, const void* src) {
    asm volatile("cp.async.cg.shared.global [%0], [%1], 16;" :: "r"(dst), "l"(src));
}
#define CP_COMMIT() asm volatile("cp.async.commit_group;" ::: "memory")
#define CP_WAIT2()  asm volatile("cp.async.wait_group 2;" ::: "memory")
#define CP_WAIT1()  asm volatile("cp.async.wait_group 1;" ::: "memory")
#define CP_WAIT0()  asm volatile("cp.async.wait_group 0;" ::: "memory")

#define LDSM4(r0, r1, r2, r3, addr)                                              \
    asm volatile("ldmatrix.sync.aligned.m8n8.x4.shared.b16 {%0,%1,%2,%3}, [%4];" \
                 : "=r"(r0), "=r"(r1), "=r"(r2), "=r"(r3) : "r"(addr))

// f16 accumulators: c[0]=row r cols (c,c+1); c[1]=row r+8.
#define MMA16816H(c, a, b0, b1)                                                \
    asm volatile("mma.sync.aligned.m16n8k16.row.col.f16.f16.f16.f16 "          \
                 "{%0,%1}, {%2,%3,%4,%5}, {%6,%7}, {%0,%1};"                   \
                 : "+r"((c)[0]), "+r"((c)[1])                                  \
                 : "r"((a)[0]), "r"((a)[1]), "r"((a)[2]), "r"((a)[3]),         \
                   "r"(b0), "r"(b1))

__device__ __forceinline__ float fast_lg2(float x) {
    float y; asm("lg2.approx.f32 %0, %1;" : "=f"(y) : "f"(x)); return y;
}
__device__ __forceinline__ __half2 u2h2(uint32_t u) {
    __half2 h; memcpy(&h, &u, 4); return h;
}

// ---------------- 1) prep ----------------
__global__ void prep_kernel(const float* __restrict__ zi, const float* __restrict__ zj) {
    int gtid = blockIdx.x * blockDim.x + threadIdx.x;
    if (gtid < N2) g_S[gtid] = 0ull;
    if (gtid == 0) { g_acc = 0ull; g_tick = 0u; }
    int w    = gtid >> 5;
    int lane = threadIdx.x & 31;
    if (w >= NHALF) return;
    float4 a = reinterpret_cast<const float4*>(zi + (size_t)w * DD)[lane];
    float4 b = reinterpret_cast<const float4*>(zj + (size_t)w * DD)[lane];
    float sa = a.x * a.x + a.y * a.y + a.z * a.z + a.w * a.w;
    float sb = b.x * b.x + b.y * b.y + b.z * b.z + b.w * b.w;
    float dp = a.x * b.x + a.y * b.y + a.z * b.z + a.w * b.w;
#pragma unroll
    for (int o = 16; o > 0; o >>= 1) {
        sa += __shfl_xor_sync(0xffffffffu, sa, o);
        sb += __shfl_xor_sync(0xffffffffu, sb, o);
        dp += __shfl_xor_sync(0xffffffffu, dp, o);
    }
    float ia = rsqrtf(sa), ib = rsqrtf(sb);
    const float CA = 2.8853900817779268f;   // 2*log2(e)
    float iaC = ia * CA, ibC = ib * CA;

    __half sA[4], pA[4], sB[4], pB[4];
    sA[0]=__float2half_rn(a.x*iaC); sA[1]=__float2half_rn(a.y*iaC);
    sA[2]=__float2half_rn(a.z*iaC); sA[3]=__float2half_rn(a.w*iaC);
    pA[0]=__float2half_rn(a.x*ia);  pA[1]=__float2half_rn(a.y*ia);
    pA[2]=__float2half_rn(a.z*ia);  pA[3]=__float2half_rn(a.w*ia);
    sB[0]=__float2half_rn(b.x*ibC); sB[1]=__float2half_rn(b.y*ibC);
    sB[2]=__float2half_rn(b.z*ibC); sB[3]=__float2half_rn(b.w*ibC);
    pB[0]=__float2half_rn(b.x*ib);  pB[1]=__float2half_rn(b.y*ib);
    pB[2]=__float2half_rn(b.z*ib);  pB[3]=__float2half_rn(b.w*ib);

    float da = 0.f, db = 0.f;
#pragma unroll
    for (int k = 0; k < 4; ++k) {
        da += __half2float(sA[k]) * __half2float(pA[k]);
        db += __half2float(sB[k]) * __half2float(pB[k]);
    }
#pragma unroll
    for (int o = 16; o > 0; o >>= 1) {
        da += __shfl_xor_sync(0xffffffffu, da, o);
        db += __shfl_xor_sync(0xffffffffu, db, o);
    }
    if (lane == 0) {
        float p = 2.0f * dp * ia * ib;
        g_pos[w] = p; g_pos[w + NHALF] = p;
        g_diag[w]         = exp2f(da);
        g_diag[w + NHALF] = exp2f(db);
    }
    uint2 u;
    memcpy(&u, sA, 8); reinterpret_cast<uint2*>(g_znA + (size_t)w * DD)[lane] = u;
    memcpy(&u, pA, 8); reinterpret_cast<uint2*>(g_znB + (size_t)w * DD)[lane] = u;
    memcpy(&u, sB, 8); reinterpret_cast<uint2*>(g_znA + (size_t)(w + NHALF) * DD)[lane] = u;
    memcpy(&u, pB, 8); reinterpret_cast<uint2*>(g_znB + (size_t)(w + NHALF) * DD)[lane] = u;
}

// ---------------- 2) fused symmetric HMMA + chunk-lagged epilogue ----------------
__device__ __forceinline__ void load_tile(uint32_t dstBase, const __half* src, int tid) {
#pragma unroll
    for (int p = 0; p < 8; ++p) {
        int id = p * 256 + tid;
        int row = id >> 4, ch = id & 15;
        cp16(dstBase + row * RSTRIDE + ch * 16,
             reinterpret_cast<const char*>(src) + row * 256 + ch * 16);
    }
}

// one 16-col chunk: 8 LDSM4 + 32 MMA into acc[2 mb][2 nb][2] (8 regs)
__device__ __forceinline__ void mma_chunk(uint32_t bBase,
                                          const uint32_t afr[2][8][4],
                                          uint32_t acc[2][2][2]) {
#pragma unroll
    for (int mb = 0; mb < 2; ++mb)
#pragma unroll
        for (int nb = 0; nb < 2; ++nb) { acc[mb][nb][0] = 0u; acc[mb][nb][1] = 0u; }
    uint32_t bfr[8][4];
#pragma unroll
    for (int ks = 0; ks < 8; ++ks)
        LDSM4(bfr[ks][0], bfr[ks][1], bfr[ks][2], bfr[ks][3],
              bBase + (uint32_t)(ks * 32));
#pragma unroll
    for (int ks = 0; ks < 8; ++ks)
#pragma unroll
        for (int mb = 0; mb < 2; ++mb) {
            MMA16816H(acc[mb][0], afr[mb][ks], bfr[ks][0], bfr[ks][1]);
            MMA16816H(acc[mb][1], afr[mb][ks], bfr[ks][2], bfr[ks][3]);
        }
}

// epilogue for a finished chunk (no dependency on in-flight MMAs)
__device__ __forceinline__ void epi_chunk(const uint32_t acc[2][2][2], int np,
                                          float frow[2][2], float* colred,
                                          int lane, int wn, int wm) {
    const __half2 zero2 = __float2half2_rn(0.f);
#pragma unroll
    for (int nb = 0; nb < 2; ++nb) {
        __half2 e00 = h2exp2(u2h2(acc[0][nb][0]));
        __half2 e01 = h2exp2(u2h2(acc[0][nb][1]));
        __half2 e10 = h2exp2(u2h2(acc[1][nb][0]));
        __half2 e11 = h2exp2(u2h2(acc[1][nb][1]));
        // rows
        float2 f;
        f = __half22float2(__hadd2(e00, zero2)); frow[0][0] += f.x + f.y;
        f = __half22float2(e01); frow[0][1] += f.x + f.y;
        f = __half22float2(e10); frow[1][0] += f.x + f.y;
        f = __half22float2(e11); frow[1][1] += f.x + f.y;
        // cols: sum 4 row-contributions, reduce over lane groups
        __half2 v = __hadd2(__hadd2(e00, e01), __hadd2(e10, e11));
        v = __hadd2(v, __shfl_xor_sync(0xffffffffu, v, 4));
        v = __hadd2(v, __shfl_xor_sync(0xffffffffu, v, 8));
        v = __hadd2(v, __shfl_xor_sync(0xffffffffu, v, 16));
        if (lane < 4) {
            float2 c = __half22float2(v);
            int col = wn * 64 + np * 16 + nb * 8 + lane * 2;
            colred[wm * 128 + col + 0] = c.x;
            colred[wm * 128 + col + 1] = c.y;
        }
    }
}

__global__ __launch_bounds__(256, 1) void simlse_kernel() {
    extern __shared__ unsigned char smem[];
    const uint32_t sb   = smem_u32(smem);
    const uint32_t smA  = sb;
    const uint32_t smB0 = sb + TILE_SM;                          // 3 stages
    float* colred = reinterpret_cast<float*>(smem + SM_COLRED);  // [4 wm][128]

    const int tid = threadIdx.x, wid = tid >> 5, lane = tid & 31;
    const int wm = wid & 3;           // 4 row groups (32 rows)
    const int wn = wid >> 2;          // 2 col groups (64 cols)
    const int bx = blockIdx.x;

    int t    = bx * 14 + (bx < 8 ? bx : 8);
    int tEnd = t + 14 + (bx < 8 ? 1 : 0);

    const uint32_t aOff = (uint32_t)(lane & 15) * RSTRIDE + (uint32_t)((lane >> 4) << 4);
    const uint32_t bOff = (uint32_t)((lane & 7) + ((lane & 16) ? 8 : 0)) * RSTRIDE +
                          (uint32_t)((lane & 8) ? 16 : 0);

#pragma unroll 1
    while (t < tEnd) {
        int q = t / 65, r = t - q * 65;
        int len1 = 64 - q;
        int I, J0, navail;
        if (r < len1) { I = q;      J0 = q + r;  navail = len1 - r; }
        else          { int r2 = r - len1;
                        I = 63 - q; J0 = I + r2; navail = (q + 1) - r2; }
        const int n = (tEnd - t < navail) ? (tEnd - t) : navail;
        t += n;

        __syncthreads();   // previous-run reads complete
        load_tile(smA, g_znA + (size_t)I * 128 * DD, tid);
        CP_COMMIT();
        load_tile(smB0, g_znB + (size_t)J0 * 128 * DD, tid);
        CP_COMMIT();
        if (n > 1)
            load_tile(smB0 + TILE_SM, g_znB + (size_t)(J0 + 1) * 128 * DD, tid);
        CP_COMMIT();
        CP_WAIT2();
        __syncthreads();

        // A fragments: 32 rows x 128 k = 64 regs
        uint32_t afr[2][8][4];
        {
            const uint32_t aBase = smA + (uint32_t)(wm * 32) * RSTRIDE + aOff;
#pragma unroll
            for (int mb = 0; mb < 2; ++mb)
#pragma unroll
                for (int ks = 0; ks < 8; ++ks)
                    LDSM4(afr[mb][ks][0], afr[mb][ks][1], afr[mb][ks][2], afr[mb][ks][3],
                          aBase + (uint32_t)(mb * 16) * RSTRIDE + (uint32_t)(ks * 32));
        }

        float frow[2][2] = {{0.f,0.f},{0.f,0.f}};

#pragma unroll 1
        for (int tt = 0; tt < n; ++tt) {
            const int J = J0 + tt;
            const int s = tt % 3;
            CP_WAIT1();
            __syncthreads();
            if (tt + 2 < n)
                load_tile(smB0 + (uint32_t)((tt + 2) % 3) * TILE_SM,
                          g_znB + (size_t)(J + 2) * 128 * DD, tid);
            CP_COMMIT();

            const uint32_t bBase = smB0 + (uint32_t)s * TILE_SM +
                                   (uint32_t)(wn * 64) * RSTRIDE + bOff;
            uint32_t acc0[2][2][2], acc1[2][2][2];
            // chunk pipeline: mma(c) overlaps epi(c-1)
            mma_chunk(bBase,                          afr, acc0);   // c0
            mma_chunk(bBase + 16u * RSTRIDE,          afr, acc1);   // c1
            epi_chunk(acc0, 0, frow, colred, lane, wn, wm);
            mma_chunk(bBase + 32u * RSTRIDE,          afr, acc0);   // c2
            epi_chunk(acc1, 1, frow, colred, lane, wn, wm);
            mma_chunk(bBase + 48u * RSTRIDE,          afr, acc1);   // c3
            epi_chunk(acc0, 2, frow, colred, lane, wn, wm);
            epi_chunk(acc1, 3, frow, colred, lane, wn, wm);

            __syncthreads();   // colred ready; stage-s reads complete
            if (J != I && tid < 128) {
                float v = colred[tid] + colred[128 + tid] +
                          colred[256 + tid] + colred[384 + tid];
                atomicAdd(&g_S[J * 128 + tid], __float2ull_rn(v * FXS));
            }
        }

        // row flush for band I (per run)
#pragma unroll
        for (int mb = 0; mb < 2; ++mb)
#pragma unroll
            for (int h = 0; h < 2; ++h) {
                frow[mb][h] += __shfl_xor_sync(0xffffffffu, frow[mb][h], 1);
                frow[mb][h] += __shfl_xor_sync(0xffffffffu, frow[mb][h], 2);
            }
        if ((lane & 3) == 0) {
            int qd = lane >> 2;
            int rbase = I * 128 + wm * 32 + qd;
#pragma unroll
            for (int mb = 0; mb < 2; ++mb) {
                atomicAdd(&g_S[rbase + mb * 16 + 0], __float2ull_rn(frow[mb][0] * FXS));
                atomicAdd(&g_S[rbase + mb * 16 + 8], __float2ull_rn(frow[mb][1] * FXS));
            }
        }
    }
    CP_WAIT0();
}

// ---------------- 3) finish: 8 blocks, last block writes ----------------
__global__ void finish_kernel(float* __restrict__ out) {
    const int t = threadIdx.x;
    const int i = blockIdx.x * 1024 + t;
    const float LN2 = 0.6931471805599453f;
    float S = __ull2float_rn(g_S[i]) * (1.0f / FXS);
    float term = fast_lg2(S - g_diag[i]) * LN2 - g_pos[i];
    unsigned long long fx = __float2ull_rn(term * FXL);
#pragma unroll
    for (int o = 16; o > 0; o >>= 1)
        fx += __shfl_xor_sync(0xffffffffu, fx, o);
    if ((t & 31) == 0) atomicAdd(&g_acc, fx);
    __threadfence();
    __syncthreads();
    if (t == 0) {
        unsigned int tk = atomicAdd(&g_tick, 1u);
        if (tk == gridDim.x - 1) {
            __threadfence();
            unsigned long long total = atomicAdd(&g_acc, 0ull);
            out[0] = (float)((double)total * (1.0 / 1099511627776.0) / (double)N2);
        }
    }
}

// ---------------- launch ----------------
extern "C" void kernel_launch(void* const* d_in, const int* in_sizes, int n_in,
                              void* d_out, int out_size) {
    const float* zi = (const float*)d_in[0];
    const float* zj = (const float*)d_in[1];
    cudaFuncSetAttribute(simlse_kernel, cudaFuncAttributeMaxDynamicSharedMemorySize,
                         SMEM_TOTAL);
    prep_kernel<<<NHALF / 8, 256>>>(zi, zj);
    simlse_kernel<<<NCTA, 256, SMEM_TOTAL>>>();
    finish_kernel<<<N2 / 1024, 1024>>>((float*)d_out);
}

// round 16
// speedup vs baseline: 1.0949x; 1.0530x over previous
#include <cuda_runtime.h>
#include <cuda_fp16.h>
#include <cstdint>
#include <cstring>

// NT-Xent contrastive loss, sm_103 baseline ISA. fp16 HMMA (f16 acc).
// KEY CHANGE: 32 independent accumulator chains of depth 4 per warp
// (K split into two interleaved halves, full 64-col warp tile live) to cover
// the legacy-HMMA accumulator RAW latency. Single zn array scaled by
// sqrt(2*log2e) on both GEMM operands. Symmetric tiles (I<=J), pair-major
// flattened 148-CTA schedule, u64 fixed-point atomics (deterministic).

#define N2    8192
#define DD    128
#define NHALF 4096
#define RSTRIDE 272
#define TILE_SM (128 * RSTRIDE)          // 34816
#define SM_COLRED (4 * TILE_SM)          // A + 3 B stages before colred
#define SMEM_TOTAL (4 * TILE_SM + 2048)  // colred = 4*128 floats
#define FXS  68719476736.0f              // 2^36
#define FXL  1099511627776.0f            // 2^40
#define NCTA 148

__device__ __align__(16) __half g_zn[(size_t)N2 * DD];   // normalize(z) * sqrt(2*log2e)
__device__ unsigned long long g_S[N2];
__device__ unsigned long long g_acc;
__device__ unsigned int g_tick;
__device__ float g_pos[N2];
__device__ float g_diag[N2];

// ---------------- PTX helpers ----------------
__device__ __forceinline__ uint32_t smem_u32(const void* p) {
    uint32_t a;
    asm("{ .reg .u64 t; cvta.to.shared.u64 t, %1; cvt.u32.u64 %0, t; }" : "=r"(a) : "l"(p));
    return a;
}
__device__ __forceinline__ void cp16(uint32_t dst, const void* src) {
    asm volatile("cp.async.cg.shared.global [%0], [%1], 16;" :: "r"(dst), "l"(src));
}
#define CP_COMMIT() asm volatile("cp.async.commit_group;" ::: "memory")
#define CP_WAIT2()  asm volatile("cp.async.wait_group 2;" ::: "memory")
#define CP_WAIT1()  asm volatile("cp.async.wait_group 1;" ::: "memory")
#define CP_WAIT0()  asm volatile("cp.async.wait_group 0;" ::: "memory")

#define LDSM4(r0, r1, r2, r3, addr)                                              \
    asm volatile("ldmatrix.sync.aligned.m8n8.x4.shared.b16 {%0,%1,%2,%3}, [%4];" \
                 : "=r"(r0), "=r"(r1), "=r"(r2), "=r"(r3) : "r"(addr))

// f16 accumulators: c[0]=row r cols (c,c+1); c[1]=row r+8.
#define MMA16816H(c, a, b0, b1)                                                \
    asm volatile("mma.sync.aligned.m16n8k16.row.col.f16.f16.f16.f16 "          \
                 "{%0,%1}, {%2,%3,%4,%5}, {%6,%7}, {%0,%1};"                   \
                 : "+r"((c)[0]), "+r"((c)[1])                                  \
                 : "r"((a)[0]), "r"((a)[1]), "r"((a)[2]), "r"((a)[3]),         \
                   "r"(b0), "r"(b1))

__device__ __forceinline__ float fast_lg2(float x) {
    float y; asm("lg2.approx.f32 %0, %1;" : "=f"(y) : "f"(x)); return y;
}
__device__ __forceinline__ __half2 u2h2(uint32_t u) {
    __half2 h; memcpy(&h, &u, 4); return h;
}

// ---------------- 1) prep: normalize -> fp16 * sqrt(2*log2e), diag, pos ------
__global__ void prep_kernel(const float* __restrict__ zi, const float* __restrict__ zj) {
    int gtid = blockIdx.x * blockDim.x + threadIdx.x;
    if (gtid < N2) g_S[gtid] = 0ull;
    if (gtid == 0) { g_acc = 0ull; g_tick = 0u; }
    int w    = gtid >> 5;
    int lane = threadIdx.x & 31;
    if (w >= NHALF) return;
    float4 a = reinterpret_cast<const float4*>(zi + (size_t)w * DD)[lane];
    float4 b = reinterpret_cast<const float4*>(zj + (size_t)w * DD)[lane];
    float sa = a.x * a.x + a.y * a.y + a.z * a.z + a.w * a.w;
    float sb = b.x * b.x + b.y * b.y + b.z * b.z + b.w * b.w;
    float dp = a.x * b.x + a.y * b.y + a.z * b.z + a.w * b.w;
#pragma unroll
    for (int o = 16; o > 0; o >>= 1) {
        sa += __shfl_xor_sync(0xffffffffu, sa, o);
        sb += __shfl_xor_sync(0xffffffffu, sb, o);
        dp += __shfl_xor_sync(0xffffffffu, dp, o);
    }
    float ia = rsqrtf(sa), ib = rsqrtf(sb);
    const float SQ = 1.69864361f;           // sqrt(2*log2(e)); SQ*SQ = 2.8853901
    float iaS = ia * SQ, ibS = ib * SQ;

    __half qa[4], qb[4];
    qa[0]=__float2half_rn(a.x*iaS); qa[1]=__float2half_rn(a.y*iaS);
    qa[2]=__float2half_rn(a.z*iaS); qa[3]=__float2half_rn(a.w*iaS);
    qb[0]=__float2half_rn(b.x*ibS); qb[1]=__float2half_rn(b.y*ibS);
    qb[2]=__float2half_rn(b.z*ibS); qb[3]=__float2half_rn(b.w*ibS);

    // self-dot of quantized values (matches the MMA's diagonal term closely)
    float da = 0.f, db = 0.f;
#pragma unroll
    for (int k = 0; k < 4; ++k) {
        float fa = __half2float(qa[k]), fb = __half2float(qb[k]);
        da += fa * fa; db += fb * fb;
    }
#pragma unroll
    for (int o = 16; o > 0; o >>= 1) {
        da += __shfl_xor_sync(0xffffffffu, da, o);
        db += __shfl_xor_sync(0xffffffffu, db, o);
    }
    if (lane == 0) {
        float p = 2.0f * dp * ia * ib;
        g_pos[w] = p; g_pos[w + NHALF] = p;
        g_diag[w]         = exp2f(da);
        g_diag[w + NHALF] = exp2f(db);
    }
    uint2 u;
    memcpy(&u, qa, 8); reinterpret_cast<uint2*>(g_zn + (size_t)w * DD)[lane] = u;
    memcpy(&u, qb, 8); reinterpret_cast<uint2*>(g_zn + (size_t)(w + NHALF) * DD)[lane] = u;
}

// ---------------- 2) fused symmetric HMMA + exp2 row/col sums ----------------
__device__ __forceinline__ void load_tile(uint32_t dstBase, const __half* src, int tid) {
#pragma unroll
    for (int p = 0; p < 8; ++p) {
        int id = p * 256 + tid;
        int row = id >> 4, ch = id & 15;
        cp16(dstBase + row * RSTRIDE + ch * 16,
             reinterpret_cast<const char*>(src) + row * 256 + ch * 16);
    }
}

__global__ __launch_bounds__(256, 1) void simlse_kernel() {
    extern __shared__ unsigned char smem[];
    const uint32_t sb   = smem_u32(smem);
    const uint32_t smA  = sb;
    const uint32_t smB0 = sb + TILE_SM;                          // 3 stages
    float* colred = reinterpret_cast<float*>(smem + SM_COLRED);  // [4 wm][128]

    const int tid = threadIdx.x, wid = tid >> 5, lane = tid & 31;
    const int wm = wid & 3;           // 4 row groups (32 rows)
    const int wn = wid >> 2;          // 2 col groups (64 cols)
    const int bx = blockIdx.x;

    int t    = bx * 14 + (bx < 8 ? bx : 8);
    int tEnd = t + 14 + (bx < 8 ? 1 : 0);

    const uint32_t aOff = (uint32_t)(lane & 15) * RSTRIDE + (uint32_t)((lane >> 4) << 4);
    const uint32_t bOff = (uint32_t)((lane & 7) + ((lane & 16) ? 8 : 0)) * RSTRIDE +
                          (uint32_t)((lane & 8) ? 16 : 0);
    const __half2 zero2 = __float2half2_rn(0.f);

#pragma unroll 1
    while (t < tEnd) {
        int q = t / 65, r = t - q * 65;
        int len1 = 64 - q;
        int I, J0, navail;
        if (r < len1) { I = q;      J0 = q + r;  navail = len1 - r; }
        else          { int r2 = r - len1;
                        I = 63 - q; J0 = I + r2; navail = (q + 1) - r2; }
        const int n = (tEnd - t < navail) ? (tEnd - t) : navail;
        t += n;

        __syncthreads();   // previous-run reads complete
        load_tile(smA, g_zn + (size_t)I * 128 * DD, tid);
        CP_COMMIT();
        load_tile(smB0, g_zn + (size_t)J0 * 128 * DD, tid);
        CP_COMMIT();
        if (n > 1)
            load_tile(smB0 + TILE_SM, g_zn + (size_t)(J0 + 1) * 128 * DD, tid);
        CP_COMMIT();
        CP_WAIT2();
        __syncthreads();

        // A fragments: 32 rows x 128 k = 64 regs
        uint32_t afr[2][8][4];
        {
            const uint32_t aBase = smA + (uint32_t)(wm * 32) * RSTRIDE + aOff;
#pragma unroll
            for (int mb = 0; mb < 2; ++mb)
#pragma unroll
                for (int ks = 0; ks < 8; ++ks)
                    LDSM4(afr[mb][ks][0], afr[mb][ks][1], afr[mb][ks][2], afr[mb][ks][3],
                          aBase + (uint32_t)(mb * 16) * RSTRIDE + (uint32_t)(ks * 32));
        }

        float frow[2][2] = {{0.f,0.f},{0.f,0.f}};

#pragma unroll 1
        for (int tt = 0; tt < n; ++tt) {
            const int J = J0 + tt;
            const int s = tt % 3;
            CP_WAIT1();
            __syncthreads();
            if (tt + 2 < n)
                load_tile(smB0 + (uint32_t)((tt + 2) % 3) * TILE_SM,
                          g_zn + (size_t)(J + 2) * 128 * DD, tid);
            CP_COMMIT();

            const uint32_t bBase = smB0 + (uint32_t)s * TILE_SM +
                                   (uint32_t)(wn * 64) * RSTRIDE + bOff;

            // 32 independent chains of depth 4: accv[half][mb][nq][nb][2]
            uint32_t accv[2][2][4][2][2];
#pragma unroll
            for (int h = 0; h < 2; ++h)
#pragma unroll
                for (int mb = 0; mb < 2; ++mb)
#pragma unroll
                    for (int nq = 0; nq < 4; ++nq)
#pragma unroll
                        for (int nb = 0; nb < 2; ++nb)
                            { accv[h][mb][nq][nb][0] = 0u; accv[h][mb][nq][nb][1] = 0u; }

            uint32_t bfr[2][4][4];   // double-buffered B fragments per ks
#pragma unroll
            for (int nq = 0; nq < 4; ++nq)
                LDSM4(bfr[0][nq][0], bfr[0][nq][1], bfr[0][nq][2], bfr[0][nq][3],
                      bBase + (uint32_t)(nq * 16) * RSTRIDE);
#pragma unroll
            for (int ks = 0; ks < 8; ++ks) {
                const int cur = ks & 1, nxt = cur ^ 1;
                if (ks + 1 < 8) {
#pragma unroll
                    for (int nq = 0; nq < 4; ++nq)
                        LDSM4(bfr[nxt][nq][0], bfr[nxt][nq][1], bfr[nxt][nq][2], bfr[nxt][nq][3],
                              bBase + (uint32_t)(nq * 16) * RSTRIDE + (uint32_t)((ks + 1) * 32));
                }
                const int h = ks & 1;   // alternate chain halves every ks
#pragma unroll
                for (int mb = 0; mb < 2; ++mb)
#pragma unroll
                    for (int nq = 0; nq < 4; ++nq) {
                        MMA16816H(accv[h][mb][nq][0], afr[mb][ks], bfr[cur][nq][0], bfr[cur][nq][1]);
                        MMA16816H(accv[h][mb][nq][1], afr[mb][ks], bfr[cur][nq][2], bfr[cur][nq][3]);
                    }
            }

            // epilogue: merge K-halves, exp2, row + col sums
            __half2 sumr0[2] = {zero2, zero2};
            __half2 sumr8[2] = {zero2, zero2};
#pragma unroll
            for (int nq = 0; nq < 4; ++nq)
#pragma unroll
                for (int nb = 0; nb < 2; ++nb) {
                    __half2 colv = zero2;
#pragma unroll
                    for (int mb = 0; mb < 2; ++mb) {
                        __half2 s0 = __hadd2(u2h2(accv[0][mb][nq][nb][0]),
                                             u2h2(accv[1][mb][nq][nb][0]));
                        __half2 s1 = __hadd2(u2h2(accv[0][mb][nq][nb][1]),
                                             u2h2(accv[1][mb][nq][nb][1]));
                        __half2 e0 = h2exp2(s0);
                        __half2 e1 = h2exp2(s1);
                        sumr0[mb] = __hadd2(sumr0[mb], e0);
                        sumr8[mb] = __hadd2(sumr8[mb], e1);
                        colv = __hadd2(colv, __hadd2(e0, e1));
                    }
                    colv = __hadd2(colv, __shfl_xor_sync(0xffffffffu, colv, 4));
                    colv = __hadd2(colv, __shfl_xor_sync(0xffffffffu, colv, 8));
                    colv = __hadd2(colv, __shfl_xor_sync(0xffffffffu, colv, 16));
                    if (lane < 4) {
                        float2 c = __half22float2(colv);
                        int col = wn * 64 + nq * 16 + nb * 8 + lane * 2;
                        colred[wm * 128 + col + 0] = c.x;
                        colred[wm * 128 + col + 1] = c.y;
                    }
                }
#pragma unroll
            for (int mb = 0; mb < 2; ++mb) {
                float2 f0 = __half22float2(sumr0[mb]);
                float2 f1 = __half22float2(sumr8[mb]);
                frow[mb][0] += f0.x + f0.y;
                frow[mb][1] += f1.x + f1.y;
            }

            __syncthreads();   // colred ready; stage-s reads complete
            if (J != I && tid < 128) {
                float v = colred[tid] + colred[128 + tid] +
                          colred[256 + tid] + colred[384 + tid];
                atomicAdd(&g_S[J * 128 + tid], __float2ull_rn(v * FXS));
            }
        }

        // row flush for band I (per run)
#pragma unroll
        for (int mb = 0; mb < 2; ++mb)
#pragma unroll
            for (int h = 0; h < 2; ++h) {
                frow[mb][h] += __shfl_xor_sync(0xffffffffu, frow[mb][h], 1);
                frow[mb][h] += __shfl_xor_sync(0xffffffffu, frow[mb][h], 2);
            }
        if ((lane & 3) == 0) {
            int qd = lane >> 2;
            int rbase = I * 128 + wm * 32 + qd;
#pragma unroll
            for (int mb = 0; mb < 2; ++mb) {
                atomicAdd(&g_S[rbase + mb * 16 + 0], __float2ull_rn(frow[mb][0] * FXS));
                atomicAdd(&g_S[rbase + mb * 16 + 8], __float2ull_rn(frow[mb][1] * FXS));
            }
        }
    }
    CP_WAIT0();
}

// ---------------- 3) finish: 8 blocks, last block writes ----------------
__global__ void finish_kernel(float* __restrict__ out) {
    const int t = threadIdx.x;
    const int i = blockIdx.x * 1024 + t;
    const float LN2 = 0.6931471805599453f;
    float S = __ull2float_rn(g_S[i]) * (1.0f / FXS);
    float term = fast_lg2(S - g_diag[i]) * LN2 - g_pos[i];
    unsigned long long fx = __float2ull_rn(term * FXL);
#pragma unroll
    for (int o = 16; o > 0; o >>= 1)
        fx += __shfl_xor_sync(0xffffffffu, fx, o);
    if ((t & 31) == 0) atomicAdd(&g_acc, fx);
    __threadfence();
    __syncthreads();
    if (t == 0) {
        unsigned int tk = atomicAdd(&g_tick, 1u);
        if (tk == gridDim.x - 1) {
            __threadfence();
            unsigned long long total = atomicAdd(&g_acc, 0ull);
            out[0] = (float)((double)total * (1.0 / 1099511627776.0) / (double)N2);
        }
    }
}

// ---------------- launch ----------------
extern "C" void kernel_launch(void* const* d_in, const int* in_sizes, int n_in,
                              void* d_out, int out_size) {
    const float* zi = (const float*)d_in[0];
    const float* zj = (const float*)d_in[1];
    cudaFuncSetAttribute(simlse_kernel, cudaFuncAttributeMaxDynamicSharedMemorySize,
                         SMEM_TOTAL);
    prep_kernel<<<NHALF / 8, 256>>>(zi, zj);
    simlse_kernel<<<NCTA, 256, SMEM_TOTAL>>>();
    finish_kernel<<<N2 / 1024, 1024>>>((float*)d_out);
}